// round 1
// baseline (speedup 1.0000x reference)
#include <cuda_runtime.h>
#include <math.h>

#define VOCAB 32000
#define EMBED 256
#define HID   256
#define BATCH 32
#define SEQ   4096
#define NCH   32            // chunks per sequence
#define CLEN  (SEQ / NCH)   // 128 timesteps per chunk

// ---- scratch (device globals; no allocation allowed) ----
__device__ float g_zfpre[VOCAB * 512];       // pre-activation table [v, 0..255=z, 256..511=f]
__device__ float g_tf[VOCAB * HID];          // sigmoid(f_pre)
__device__ float g_tg[VOCAB * HID];          // (1-f)*tanh(z_pre)
__device__ float g_P[BATCH * NCH * HID];     // chunk decay product
__device__ float g_E[BATCH * NCH * HID];     // chunk local scan end (h0=0)
__device__ float g_cm[BATCH * NCH];          // chunk softmax max
__device__ float g_cd[BATCH * NCH];          // chunk softmax denom
__device__ float g_cacc[BATCH * NCH * HID];  // chunk weighted h accumulator

// ============================================================
// K0: vocab table GEMM   C[v,n] = dot(emb[v,:], conv_w[n,:])
//     M=32000, N=512, K=256, fp32, BM=BN=64, BK=16, 256 thr, 4x4 micro
// ============================================================
__global__ __launch_bounds__(256) void k_gemm(const float* __restrict__ emb,
                                              const float* __restrict__ cw) {
    __shared__ float As[16 * 65];
    __shared__ float Bs[16 * 65];
    const int m0 = blockIdx.y * 64;
    const int n0 = blockIdx.x * 64;
    const int t  = threadIdx.x;
    const int lr = t >> 2;           // 0..63 row within tile
    const int lc = (t & 3) * 4;      // 0,4,8,12 k offset
    const int ty = t >> 4;           // 0..15
    const int tx = t & 15;           // 0..15

    float acc[4][4];
#pragma unroll
    for (int i = 0; i < 4; i++)
#pragma unroll
        for (int j = 0; j < 4; j++) acc[i][j] = 0.f;

    for (int k0 = 0; k0 < EMBED; k0 += 16) {
        float4 a = *(const float4*)(emb + (size_t)(m0 + lr) * EMBED + k0 + lc);
        float4 b = *(const float4*)(cw  + (size_t)(n0 + lr) * EMBED + k0 + lc);
        As[(lc + 0) * 65 + lr] = a.x; As[(lc + 1) * 65 + lr] = a.y;
        As[(lc + 2) * 65 + lr] = a.z; As[(lc + 3) * 65 + lr] = a.w;
        Bs[(lc + 0) * 65 + lr] = b.x; Bs[(lc + 1) * 65 + lr] = b.y;
        Bs[(lc + 2) * 65 + lr] = b.z; Bs[(lc + 3) * 65 + lr] = b.w;
        __syncthreads();
#pragma unroll
        for (int k = 0; k < 16; k++) {
            float ar[4], br[4];
#pragma unroll
            for (int i = 0; i < 4; i++) ar[i] = As[k * 65 + ty * 4 + i];
#pragma unroll
            for (int j = 0; j < 4; j++) br[j] = Bs[k * 65 + tx * 4 + j];
#pragma unroll
            for (int i = 0; i < 4; i++)
#pragma unroll
                for (int j = 0; j < 4; j++) acc[i][j] = fmaf(ar[i], br[j], acc[i][j]);
        }
        __syncthreads();
    }
#pragma unroll
    for (int i = 0; i < 4; i++)
#pragma unroll
        for (int j = 0; j < 4; j++)
            g_zfpre[(size_t)(m0 + ty * 4 + i) * 512 + (n0 + tx * 4 + j)] = acc[i][j];
}

// ============================================================
// K1: activation -> tf, tg tables (adds bias here)
// ============================================================
__global__ __launch_bounds__(256) void k_act(const float* __restrict__ cb) {
    int idx = blockIdx.x * 256 + threadIdx.x;   // over VOCAB*HID
    int v = idx >> 8, h = idx & 255;
    float zp = g_zfpre[(size_t)v * 512 + h]       + cb[h];
    float fp = g_zfpre[(size_t)v * 512 + 256 + h] + cb[256 + h];
    float f  = 1.f / (1.f + expf(-fp));
    g_tf[idx] = f;
    g_tg[idx] = (1.f - f) * tanhf(zp);
}

// ============================================================
// K2: per-chunk scan summaries  (P = prod f, E = local scan from 0)
//     block = (chunk, batch), thread = channel
// ============================================================
__global__ __launch_bounds__(256) void k_summary(const int* __restrict__ X) {
    const int b = blockIdx.y, c = blockIdx.x, h = threadIdx.x;
    __shared__ int xs[CLEN];
    if (h < CLEN) xs[h] = X[b * SEQ + c * CLEN + h];
    __syncthreads();
    float P = 1.f, E = 0.f;
#pragma unroll 8
    for (int t = 0; t < CLEN; t++) {
        int base = xs[t] * HID + h;
        float f = g_tf[base];
        float g = g_tg[base];
        E = fmaf(f, E, g);
        P *= f;
    }
    int o = (b * NCH + c) * HID + h;
    g_P[o] = P;
    g_E[o] = E;
}

// ============================================================
// K3: replay each chunk with correct h_init; online softmax pooling
// ============================================================
__global__ __launch_bounds__(256) void k_main(const int* __restrict__ X,
                                              const float* __restrict__ Mu) {
    const int b = blockIdx.y, c = blockIdx.x;
    const int tid = threadIdx.x, h = threadIdx.x;
    __shared__ int   xs[CLEN];
    __shared__ float sred[8 * 257];
    __shared__ float lv[8];

    if (tid < CLEN) xs[tid] = X[b * SEQ + c * CLEN + tid];

    // reconstruct h at chunk start from summaries of chunks 0..c-1
    float hv = 0.f;
    for (int cc = 0; cc < c; cc++) {
        int o = (b * NCH + cc) * HID + h;
        hv = fmaf(g_P[o], hv, g_E[o]);
    }
    const float mu = Mu[h];
    __syncthreads();

    float m = -1e30f, d = 0.f, acc = 0.f;
    for (int t0 = 0; t0 < CLEN; t0 += 8) {
        float hb[8];
#pragma unroll
        for (int j = 0; j < 8; j++) {
            int base = xs[t0 + j] * HID + h;
            hv = fmaf(g_tf[base], hv, g_tg[base]);
            hb[j] = hv;
            sred[j * 257 + tid] = hv * mu;
        }
        __syncthreads();
        {   // warp w reduces logit for timestep j=w
            int w = tid >> 5, lane = tid & 31;
            float s = 0.f;
#pragma unroll
            for (int k = 0; k < 8; k++) s += sred[w * 257 + lane + k * 32];
#pragma unroll
            for (int off = 16; off; off >>= 1) s += __shfl_xor_sync(0xffffffffu, s, off);
            if (lane == 0) lv[w] = s;
        }
        __syncthreads();
#pragma unroll
        for (int j = 0; j < 8; j++) {
            float l  = lv[j];
            float mn = fmaxf(m, l);
            float sc = expf(m - mn);
            float wg = expf(l - mn);
            d   = d   * sc + wg;
            acc = acc * sc + hb[j] * wg;
            m = mn;
        }
    }
    if (tid == 0) { g_cm[b * NCH + c] = m; g_cd[b * NCH + c] = d; }
    g_cacc[(b * NCH + c) * HID + h] = acc;
}

// ============================================================
// K4: combine chunks per batch, context dot W_out + bias
// ============================================================
__global__ __launch_bounds__(256) void k_combine(const float* __restrict__ Wout,
                                                 const float* __restrict__ bout,
                                                 float* __restrict__ out) {
    const int b = blockIdx.x, tid = threadIdx.x, h = threadIdx.x;
    __shared__ float cm[NCH], cd[NCH], wsum[8];
    if (tid < NCH) {
        cm[tid] = g_cm[b * NCH + tid];
        cd[tid] = g_cd[b * NCH + tid];
    }
    __syncthreads();
    float M = -1e30f;
#pragma unroll
    for (int c = 0; c < NCH; c++) M = fmaxf(M, cm[c]);
    float D = 0.f, ctx = 0.f;
#pragma unroll
    for (int c = 0; c < NCH; c++) {
        float w = expf(cm[c] - M);
        D += cd[c] * w;
        ctx = fmaf(g_cacc[(b * NCH + c) * HID + h], w, ctx);
    }
    float p = (ctx / D) * Wout[h];
#pragma unroll
    for (int off = 16; off; off >>= 1) p += __shfl_xor_sync(0xffffffffu, p, off);
    if ((tid & 31) == 0) wsum[tid >> 5] = p;
    __syncthreads();
    if (tid == 0) {
        float v = 0.f;
#pragma unroll
        for (int w = 0; w < 8; w++) v += wsum[w];
        out[b] = v + bout[0];
    }
}

// ============================================================
extern "C" void kernel_launch(void* const* d_in, const int* in_sizes, int n_in,
                              void* d_out, int out_size) {
    const int*   X    = (const int*)d_in[0];
    const float* emb  = (const float*)d_in[1];
    const float* cw   = (const float*)d_in[2];
    const float* cb   = (const float*)d_in[3];
    const float* Mu   = (const float*)d_in[4];
    const float* Wout = (const float*)d_in[5];
    const float* bout = (const float*)d_in[6];
    float* out = (float*)d_out;

    k_gemm   <<<dim3(8, VOCAB / 64), 256>>>(emb, cw);
    k_act    <<<(VOCAB * HID) / 256, 256>>>(cb);
    k_summary<<<dim3(NCH, BATCH), 256>>>(X);
    k_main   <<<dim3(NCH, BATCH), 256>>>(X, Mu);
    k_combine<<<BATCH, 256>>>(Wout, bout, out);
}

// round 3
// speedup vs baseline: 2.1557x; 2.1557x over previous
#include <cuda_runtime.h>
#include <cuda_bf16.h>
#include <cuda_fp16.h>
#include <math.h>

#define VOCAB 32000
#define EMBED 256
#define HID   256
#define BATCH 32
#define SEQ   4096
#define NCH   64
#define CLEN  (SEQ / NCH)   // 64

// ---- scratch (device globals; no allocation allowed) ----
__device__ __half2 g_tab[VOCAB * HID];       // packed (f, g) per (vocab, channel)
__device__ float g_P[BATCH * NCH * HID];     // chunk decay product
__device__ float g_E[BATCH * NCH * HID];     // chunk local scan end (h0=0)
__device__ float g_cm[BATCH * NCH];          // chunk softmax max
__device__ float g_cd[BATCH * NCH];          // chunk softmax denom
__device__ float g_cacc[BATCH * NCH * HID];  // chunk weighted h accumulator

// ============================================================
// K0: vocab table GEMM on tensor cores (bf16 split precision)
//     C[v,n] = dot(emb[v,:], cw[map(n),:]) ; map pairs z/f cols.
//     BM=128, BN=64 (32 z-cols + 32 f-cols), BK=32, 8 warps.
//     Epilogue fuses bias + sigmoid/tanh and packs half2 table.
// ============================================================
#define BM 128
#define BN 64
#define BK 32
#define ASTR 40   // bf16 elems per A row in smem (pad to kill conflicts)
#define BSTR 40

struct GemmSmem {
    union {
        struct {
            __nv_bfloat16 Ah[BM * ASTR];
            __nv_bfloat16 Al[BM * ASTR];
            __nv_bfloat16 Bh[BN * BSTR];
            __nv_bfloat16 Bl[BN * BSTR];
        } s;
        float Cs[BM * 66];
    } u;
};

#define MMA_BF16(d, a, b) \
    asm volatile("mma.sync.aligned.m16n8k16.row.col.f32.bf16.bf16.f32 " \
                 "{%0,%1,%2,%3},{%4,%5,%6,%7},{%8,%9},{%0,%1,%2,%3};" \
                 : "+f"(d[0]), "+f"(d[1]), "+f"(d[2]), "+f"(d[3]) \
                 : "r"(a[0]), "r"(a[1]), "r"(a[2]), "r"(a[3]), "r"(b[0]), "r"(b[1]))

__global__ __launch_bounds__(256) void k_gemm(const float* __restrict__ emb,
                                              const float* __restrict__ cw,
                                              const float* __restrict__ cb) {
    __shared__ GemmSmem sm;
    const int t  = threadIdx.x;
    const int m0 = blockIdx.y * BM;
    const int h0 = blockIdx.x * 32;
    const int wid = t >> 5, lane = t & 31;
    const int wm = wid >> 1, wn = wid & 1;     // 4 x 2 warp grid
    const int lr = lane >> 2, lc = lane & 3;

    float acc[2][4][4];
#pragma unroll
    for (int i = 0; i < 2; i++)
#pragma unroll
        for (int j = 0; j < 4; j++)
#pragma unroll
            for (int r = 0; r < 4; r++) acc[i][j][r] = 0.f;

    // per-thread global load slots
    int arow[4], ac4[4], brow[2], bc4[2], bgr[2];
#pragma unroll
    for (int i = 0; i < 4; i++) { int l = i * 256 + t; arow[i] = l >> 3; ac4[i] = l & 7; }
#pragma unroll
    for (int i = 0; i < 2; i++) {
        int l = i * 256 + t; brow[i] = l >> 3; bc4[i] = l & 7;
        bgr[i] = (brow[i] < 32) ? (h0 + brow[i]) : (224 + h0 + brow[i]);
    }

    float4 ar[4], br[2];
#pragma unroll
    for (int i = 0; i < 4; i++)
        ar[i] = *(const float4*)(emb + (size_t)(m0 + arow[i]) * EMBED + ac4[i] * 4);
#pragma unroll
    for (int i = 0; i < 2; i++)
        br[i] = *(const float4*)(cw + (size_t)bgr[i] * EMBED + bc4[i] * 4);

    for (int kk = 0; kk < EMBED / BK; kk++) {
        // stage regs -> smem with hi/lo bf16 split
#pragma unroll
        for (int i = 0; i < 4; i++) {
            float v[4] = {ar[i].x, ar[i].y, ar[i].z, ar[i].w};
#pragma unroll
            for (int e = 0; e < 4; e++) {
                __nv_bfloat16 hi = __float2bfloat16(v[e]);
                __nv_bfloat16 lo = __float2bfloat16(v[e] - __bfloat162float(hi));
                sm.u.s.Ah[arow[i] * ASTR + ac4[i] * 4 + e] = hi;
                sm.u.s.Al[arow[i] * ASTR + ac4[i] * 4 + e] = lo;
            }
        }
#pragma unroll
        for (int i = 0; i < 2; i++) {
            float v[4] = {br[i].x, br[i].y, br[i].z, br[i].w};
#pragma unroll
            for (int e = 0; e < 4; e++) {
                __nv_bfloat16 hi = __float2bfloat16(v[e]);
                __nv_bfloat16 lo = __float2bfloat16(v[e] - __bfloat162float(hi));
                sm.u.s.Bh[brow[i] * BSTR + bc4[i] * 4 + e] = hi;
                sm.u.s.Bl[brow[i] * BSTR + bc4[i] * 4 + e] = lo;
            }
        }
        __syncthreads();

        if (kk + 1 < EMBED / BK) {
            int k0 = (kk + 1) * BK;
#pragma unroll
            for (int i = 0; i < 4; i++)
                ar[i] = *(const float4*)(emb + (size_t)(m0 + arow[i]) * EMBED + k0 + ac4[i] * 4);
#pragma unroll
            for (int i = 0; i < 2; i++)
                br[i] = *(const float4*)(cw + (size_t)bgr[i] * EMBED + k0 + bc4[i] * 4);
        }

#pragma unroll
        for (int kc = 0; kc < 2; kc++) {
            unsigned afh[2][4], afl[2][4];
#pragma unroll
            for (int mt = 0; mt < 2; mt++) {
                int r = wm * 32 + mt * 16 + lr;
                int base = r * ASTR + kc * 16 + 2 * lc;
                afh[mt][0] = *(const unsigned*)&sm.u.s.Ah[base];
                afh[mt][1] = *(const unsigned*)&sm.u.s.Ah[base + 8 * ASTR];
                afh[mt][2] = *(const unsigned*)&sm.u.s.Ah[base + 8];
                afh[mt][3] = *(const unsigned*)&sm.u.s.Ah[base + 8 * ASTR + 8];
                afl[mt][0] = *(const unsigned*)&sm.u.s.Al[base];
                afl[mt][1] = *(const unsigned*)&sm.u.s.Al[base + 8 * ASTR];
                afl[mt][2] = *(const unsigned*)&sm.u.s.Al[base + 8];
                afl[mt][3] = *(const unsigned*)&sm.u.s.Al[base + 8 * ASTR + 8];
            }
            unsigned bfh[4][2], bfl[4][2];
#pragma unroll
            for (int nt = 0; nt < 4; nt++) {
                int n = wn * 32 + nt * 8 + lr;
                int base = n * BSTR + kc * 16 + 2 * lc;
                bfh[nt][0] = *(const unsigned*)&sm.u.s.Bh[base];
                bfh[nt][1] = *(const unsigned*)&sm.u.s.Bh[base + 8];
                bfl[nt][0] = *(const unsigned*)&sm.u.s.Bl[base];
                bfl[nt][1] = *(const unsigned*)&sm.u.s.Bl[base + 8];
            }
#pragma unroll
            for (int mt = 0; mt < 2; mt++)
#pragma unroll
                for (int nt = 0; nt < 4; nt++) {
                    MMA_BF16(acc[mt][nt], afh[mt], bfh[nt]);
                    MMA_BF16(acc[mt][nt], afh[mt], bfl[nt]);
                    MMA_BF16(acc[mt][nt], afl[mt], bfh[nt]);
                }
        }
        __syncthreads();
    }

    // epilogue: stash fp32 tiles, then activation + half2 pack
#pragma unroll
    for (int mt = 0; mt < 2; mt++)
#pragma unroll
        for (int nt = 0; nt < 4; nt++) {
            int r = wm * 32 + mt * 16 + lr;
            int col = wn * 32 + nt * 8 + 2 * lc;
            sm.u.Cs[r * 66 + col]           = acc[mt][nt][0];
            sm.u.Cs[r * 66 + col + 1]       = acc[mt][nt][1];
            sm.u.Cs[(r + 8) * 66 + col]     = acc[mt][nt][2];
            sm.u.Cs[(r + 8) * 66 + col + 1] = acc[mt][nt][3];
        }
    __syncthreads();

#pragma unroll
    for (int i = 0; i < 16; i++) {
        int o = i * 256 + t;
        int v = o >> 5, h = o & 31;
        float zp = sm.u.Cs[v * 66 + h]      + cb[h0 + h];
        float fp = sm.u.Cs[v * 66 + 32 + h] + cb[256 + h0 + h];
        float f  = 1.f / (1.f + expf(-fp));
        float g  = (1.f - f) * tanhf(zp);
        g_tab[(size_t)(m0 + v) * HID + h0 + h] = __floats2half2_rn(f, g);
    }
}

// ============================================================
// K2: per-chunk scan summaries  (P = prod f, E = local scan from 0)
// ============================================================
__global__ __launch_bounds__(256) void k_summary(const int* __restrict__ X) {
    const int b = blockIdx.y, c = blockIdx.x, h = threadIdx.x;
    __shared__ int xs[CLEN];
    if (h < CLEN) xs[h] = X[b * SEQ + c * CLEN + h];
    __syncthreads();
    float P = 1.f, E = 0.f;
#pragma unroll 8
    for (int t = 0; t < CLEN; t++) {
        float2 fg = __half22float2(g_tab[(size_t)xs[t] * HID + h]);
        E = fmaf(fg.x, E, fg.y);
        P *= fg.x;
    }
    int o = (b * NCH + c) * HID + h;
    g_P[o] = P;
    g_E[o] = E;
}

// ============================================================
// K3: replay each chunk with correct h_init; online softmax pooling
// ============================================================
__global__ __launch_bounds__(256) void k_main(const int* __restrict__ X,
                                              const float* __restrict__ Mu) {
    const int b = blockIdx.y, c = blockIdx.x;
    const int tid = threadIdx.x, h = threadIdx.x;
    __shared__ int   xs[CLEN];
    __shared__ float sred[8 * 257];
    __shared__ float lv[8];

    if (tid < CLEN) xs[tid] = X[b * SEQ + c * CLEN + tid];

    // reconstruct h at chunk start from summaries of chunks 0..c-1
    float hv = 0.f;
    for (int cc = 0; cc < c; cc++) {
        int o = (b * NCH + cc) * HID + h;
        hv = fmaf(g_P[o], hv, g_E[o]);
    }
    const float mu = Mu[h];
    __syncthreads();

    float m = -1e30f, d = 0.f, acc = 0.f;
    for (int t0 = 0; t0 < CLEN; t0 += 8) {
        float hb[8];
#pragma unroll
        for (int j = 0; j < 8; j++) {
            float2 fg = __half22float2(g_tab[(size_t)xs[t0 + j] * HID + h]);
            hv = fmaf(fg.x, hv, fg.y);
            hb[j] = hv;
            sred[j * 257 + tid] = hv * mu;
        }
        __syncthreads();
        {   // warp w reduces logit for timestep j=w
            int w = tid >> 5, lane = tid & 31;
            float s = 0.f;
#pragma unroll
            for (int k = 0; k < 8; k++) s += sred[w * 257 + lane + k * 32];
#pragma unroll
            for (int off = 16; off; off >>= 1) s += __shfl_xor_sync(0xffffffffu, s, off);
            if (lane == 0) lv[w] = s;
        }
        __syncthreads();
#pragma unroll
        for (int j = 0; j < 8; j++) {
            float l  = lv[j];
            float mn = fmaxf(m, l);
            float sc = expf(m - mn);
            float wg = expf(l - mn);
            d   = d   * sc + wg;
            acc = acc * sc + hb[j] * wg;
            m = mn;
        }
    }
    if (tid == 0) { g_cm[b * NCH + c] = m; g_cd[b * NCH + c] = d; }
    g_cacc[(b * NCH + c) * HID + h] = acc;
}

// ============================================================
// K4: combine chunks per batch, context dot W_out + bias
// ============================================================
__global__ __launch_bounds__(256) void k_combine(const float* __restrict__ Wout,
                                                 const float* __restrict__ bout,
                                                 float* __restrict__ out) {
    const int b = blockIdx.x, tid = threadIdx.x, h = threadIdx.x;
    __shared__ float cm[NCH], cd[NCH], wsum[8];
    if (tid < NCH) {
        cm[tid] = g_cm[b * NCH + tid];
        cd[tid] = g_cd[b * NCH + tid];
    }
    __syncthreads();
    float M = -1e30f;
#pragma unroll
    for (int c = 0; c < NCH; c++) M = fmaxf(M, cm[c]);
    float D = 0.f, ctx = 0.f;
#pragma unroll
    for (int c = 0; c < NCH; c++) {
        float w = expf(cm[c] - M);
        D += cd[c] * w;
        ctx = fmaf(g_cacc[(b * NCH + c) * HID + h], w, ctx);
    }
    float p = (ctx / D) * Wout[h];
#pragma unroll
    for (int off = 16; off; off >>= 1) p += __shfl_xor_sync(0xffffffffu, p, off);
    if ((tid & 31) == 0) wsum[tid >> 5] = p;
    __syncthreads();
    if (tid == 0) {
        float v = 0.f;
#pragma unroll
        for (int w = 0; w < 8; w++) v += wsum[w];
        out[b] = v + bout[0];
    }
}

// ============================================================
extern "C" void kernel_launch(void* const* d_in, const int* in_sizes, int n_in,
                              void* d_out, int out_size) {
    const int*   X    = (const int*)d_in[0];
    const float* emb  = (const float*)d_in[1];
    const float* cw   = (const float*)d_in[2];
    const float* cb   = (const float*)d_in[3];
    const float* Mu   = (const float*)d_in[4];
    const float* Wout = (const float*)d_in[5];
    const float* bout = (const float*)d_in[6];
    float* out = (float*)d_out;

    k_gemm   <<<dim3(HID / 32, VOCAB / BM), 256>>>(emb, cw, cb);
    k_summary<<<dim3(NCH, BATCH), 256>>>(X);
    k_main   <<<dim3(NCH, BATCH), 256>>>(X, Mu);
    k_combine<<<BATCH, 256>>>(Wout, bout, out);
}

// round 6
// speedup vs baseline: 2.7182x; 1.2609x over previous
#include <cuda_runtime.h>
#include <cuda_fp16.h>
#include <math.h>

#define VOCAB 32000
#define EMBED 256
#define HID   256
#define BATCH 32
#define SEQ   4096
#define NCH   64
#define CLEN  (SEQ / NCH)   // 64

// ---- scratch (device globals; no allocation allowed) ----
__device__ __half2 g_tab[VOCAB * HID];       // packed (f, g) per (vocab, channel)
__device__ float g_P[BATCH * NCH * HID];     // chunk decay product
__device__ float g_E[BATCH * NCH * HID];     // chunk local scan end (h0=0)
__device__ float g_cm[BATCH * NCH];          // chunk softmax max
__device__ float g_cd[BATCH * NCH];          // chunk softmax denom
__device__ float g_cacc[BATCH * NCH * HID];  // chunk weighted h accumulator

// ============================================================
// K0: vocab table GEMM on tensor cores (single-pass fp16)
//     C[v,n] = dot(emb[v,:], cw[map(n),:]) ; map pairs z/f cols.
//     BM=128, BN=64 (32 z-cols + 32 f-cols), BK=32, 8 warps.
//     Epilogue fuses bias + sigmoid/tanh and packs half2 table.
// ============================================================
#define BM 128
#define BN 64
#define BK 32
#define ASTR 40   // half elems per A row in smem (pad to kill conflicts)
#define BSTR 40

struct GemmSmem {
    union {
        struct {
            __half Ah[BM * ASTR];
            __half Bh[BN * BSTR];
        } s;
        float Cs[BM * 66];
    } u;
};

#define MMA_F16(d, a, b) \
    asm volatile("mma.sync.aligned.m16n8k16.row.col.f32.f16.f16.f32 " \
                 "{%0,%1,%2,%3},{%4,%5,%6,%7},{%8,%9},{%0,%1,%2,%3};" \
                 : "+f"(d[0]), "+f"(d[1]), "+f"(d[2]), "+f"(d[3]) \
                 : "r"(a[0]), "r"(a[1]), "r"(a[2]), "r"(a[3]), "r"(b[0]), "r"(b[1]))

__global__ __launch_bounds__(256) void k_gemm(const float* __restrict__ emb,
                                              const float* __restrict__ cw,
                                              const float* __restrict__ cb) {
    __shared__ GemmSmem sm;
    const int t  = threadIdx.x;
    const int m0 = blockIdx.y * BM;
    const int h0 = blockIdx.x * 32;
    const int wid = t >> 5, lane = t & 31;
    const int wm = wid >> 1, wn = wid & 1;     // 4 x 2 warp grid
    const int lr = lane >> 2, lc = lane & 3;

    float acc[2][4][4];
#pragma unroll
    for (int i = 0; i < 2; i++)
#pragma unroll
        for (int j = 0; j < 4; j++)
#pragma unroll
            for (int r = 0; r < 4; r++) acc[i][j][r] = 0.f;

    // per-thread global load slots
    int arow[4], ac4[4], brow[2], bc4[2], bgr[2];
#pragma unroll
    for (int i = 0; i < 4; i++) { int l = i * 256 + t; arow[i] = l >> 3; ac4[i] = l & 7; }
#pragma unroll
    for (int i = 0; i < 2; i++) {
        int l = i * 256 + t; brow[i] = l >> 3; bc4[i] = l & 7;
        bgr[i] = (brow[i] < 32) ? (h0 + brow[i]) : (224 + h0 + brow[i]);
    }

    float4 ar[4], br[2];
#pragma unroll
    for (int i = 0; i < 4; i++)
        ar[i] = *(const float4*)(emb + (size_t)(m0 + arow[i]) * EMBED + ac4[i] * 4);
#pragma unroll
    for (int i = 0; i < 2; i++)
        br[i] = *(const float4*)(cw + (size_t)bgr[i] * EMBED + bc4[i] * 4);

    for (int kk = 0; kk < EMBED / BK; kk++) {
        // stage regs -> smem as fp16
#pragma unroll
        for (int i = 0; i < 4; i++) {
            int base = arow[i] * ASTR + ac4[i] * 4;
            *(__half2*)&sm.u.s.Ah[base]     = __floats2half2_rn(ar[i].x, ar[i].y);
            *(__half2*)&sm.u.s.Ah[base + 2] = __floats2half2_rn(ar[i].z, ar[i].w);
        }
#pragma unroll
        for (int i = 0; i < 2; i++) {
            int base = brow[i] * BSTR + bc4[i] * 4;
            *(__half2*)&sm.u.s.Bh[base]     = __floats2half2_rn(br[i].x, br[i].y);
            *(__half2*)&sm.u.s.Bh[base + 2] = __floats2half2_rn(br[i].z, br[i].w);
        }
        __syncthreads();

        if (kk + 1 < EMBED / BK) {
            int k0 = (kk + 1) * BK;
#pragma unroll
            for (int i = 0; i < 4; i++)
                ar[i] = *(const float4*)(emb + (size_t)(m0 + arow[i]) * EMBED + k0 + ac4[i] * 4);
#pragma unroll
            for (int i = 0; i < 2; i++)
                br[i] = *(const float4*)(cw + (size_t)bgr[i] * EMBED + k0 + bc4[i] * 4);
        }

#pragma unroll
        for (int kc = 0; kc < 2; kc++) {
            unsigned af[2][4];
#pragma unroll
            for (int mt = 0; mt < 2; mt++) {
                int r = wm * 32 + mt * 16 + lr;
                int base = r * ASTR + kc * 16 + 2 * lc;
                af[mt][0] = *(const unsigned*)&sm.u.s.Ah[base];
                af[mt][1] = *(const unsigned*)&sm.u.s.Ah[base + 8 * ASTR];
                af[mt][2] = *(const unsigned*)&sm.u.s.Ah[base + 8];
                af[mt][3] = *(const unsigned*)&sm.u.s.Ah[base + 8 * ASTR + 8];
            }
            unsigned bf[4][2];
#pragma unroll
            for (int nt = 0; nt < 4; nt++) {
                int n = wn * 32 + nt * 8 + lr;
                int base = n * BSTR + kc * 16 + 2 * lc;
                bf[nt][0] = *(const unsigned*)&sm.u.s.Bh[base];
                bf[nt][1] = *(const unsigned*)&sm.u.s.Bh[base + 8];
            }
#pragma unroll
            for (int mt = 0; mt < 2; mt++)
#pragma unroll
                for (int nt = 0; nt < 4; nt++)
                    MMA_F16(acc[mt][nt], af[mt], bf[nt]);
        }
        __syncthreads();
    }

    // epilogue: stash fp32 tiles, then activation + half2 pack
#pragma unroll
    for (int mt = 0; mt < 2; mt++)
#pragma unroll
        for (int nt = 0; nt < 4; nt++) {
            int r = wm * 32 + mt * 16 + lr;
            int col = wn * 32 + nt * 8 + 2 * lc;
            sm.u.Cs[r * 66 + col]           = acc[mt][nt][0];
            sm.u.Cs[r * 66 + col + 1]       = acc[mt][nt][1];
            sm.u.Cs[(r + 8) * 66 + col]     = acc[mt][nt][2];
            sm.u.Cs[(r + 8) * 66 + col + 1] = acc[mt][nt][3];
        }
    __syncthreads();

#pragma unroll
    for (int i = 0; i < 16; i++) {
        int o = i * 256 + t;
        int v = o >> 5, h = o & 31;
        float zp = sm.u.Cs[v * 66 + h]      + cb[h0 + h];
        float fp = sm.u.Cs[v * 66 + 32 + h] + cb[256 + h0 + h];
        float f  = 1.f / (1.f + expf(-fp));
        float g  = (1.f - f) * tanhf(zp);
        g_tab[(size_t)(m0 + v) * HID + h0 + h] = __floats2half2_rn(f, g);
    }
}

// ============================================================
// K2: per-chunk scan summaries  (P = prod f, E = local scan from 0)
// ============================================================
__global__ __launch_bounds__(256) void k_summary(const int* __restrict__ X) {
    const int b = blockIdx.y, c = blockIdx.x, h = threadIdx.x;
    __shared__ int xs[CLEN];
    if (h < CLEN) xs[h] = X[b * SEQ + c * CLEN + h];
    __syncthreads();
    float P = 1.f, E = 0.f;
#pragma unroll 8
    for (int t = 0; t < CLEN; t++) {
        float2 fg = __half22float2(g_tab[(size_t)xs[t] * HID + h]);
        E = fmaf(fg.x, E, fg.y);
        P *= fg.x;
    }
    int o = (b * NCH + c) * HID + h;
    g_P[o] = P;
    g_E[o] = E;
}

// ============================================================
// K3: replay each chunk with correct h_init; online softmax pooling
// ============================================================
__global__ __launch_bounds__(256) void k_main(const int* __restrict__ X,
                                              const float* __restrict__ Mu) {
    const int b = blockIdx.y, c = blockIdx.x;
    const int tid = threadIdx.x, h = threadIdx.x;
    __shared__ int   xs[CLEN];
    __shared__ float sred[8 * 257];
    __shared__ float lv[8];

    if (tid < CLEN) xs[tid] = X[b * SEQ + c * CLEN + tid];

    // reconstruct h at chunk start from summaries of chunks 0..c-1
    float hv = 0.f;
    for (int cc = 0; cc < c; cc++) {
        int o = (b * NCH + cc) * HID + h;
        hv = fmaf(g_P[o], hv, g_E[o]);
    }
    const float mu = Mu[h];
    __syncthreads();

    float m = -1e30f, d = 0.f, acc = 0.f;
    for (int t0 = 0; t0 < CLEN; t0 += 8) {
        float hb[8];
#pragma unroll
        for (int j = 0; j < 8; j++) {
            float2 fg = __half22float2(g_tab[(size_t)xs[t0 + j] * HID + h]);
            hv = fmaf(fg.x, hv, fg.y);
            hb[j] = hv;
            sred[j * 257 + tid] = hv * mu;
        }
        __syncthreads();
        {   // warp w reduces logit for timestep j=w
            int w = tid >> 5, lane = tid & 31;
            float s = 0.f;
#pragma unroll
            for (int k = 0; k < 8; k++) s += sred[w * 257 + lane + k * 32];
#pragma unroll
            for (int off = 16; off; off >>= 1) s += __shfl_xor_sync(0xffffffffu, s, off);
            if (lane == 0) lv[w] = s;
        }
        __syncthreads();
#pragma unroll
        for (int j = 0; j < 8; j++) {
            float l  = lv[j];
            float mn = fmaxf(m, l);
            float sc = expf(m - mn);
            float wg = expf(l - mn);
            d   = d   * sc + wg;
            acc = acc * sc + hb[j] * wg;
            m = mn;
        }
    }
    if (tid == 0) { g_cm[b * NCH + c] = m; g_cd[b * NCH + c] = d; }
    g_cacc[(b * NCH + c) * HID + h] = acc;
}

// ============================================================
// K4: combine chunks per batch, context dot W_out + bias
//     1024 threads: 4 chunk-quarters in parallel, then merge.
// ============================================================
__global__ __launch_bounds__(1024) void k_combine(const float* __restrict__ Wout,
                                                  const float* __restrict__ bout,
                                                  float* __restrict__ out) {
    const int b = blockIdx.x, tid = threadIdx.x;
    const int q = tid >> 8, h = tid & 255;
    __shared__ float cm[NCH], cd[NCH];
    __shared__ float part[4][256];
    __shared__ float wsum[8];
    if (tid < NCH) {
        cm[tid] = g_cm[b * NCH + tid];
        cd[tid] = g_cd[b * NCH + tid];
    }
    __syncthreads();
    float M = -1e30f;
#pragma unroll
    for (int c = 0; c < NCH; c++) M = fmaxf(M, cm[c]);
    float D = 0.f;
#pragma unroll
    for (int c = 0; c < NCH; c++) D += cd[c] * expf(cm[c] - M);

    float ctx = 0.f;
#pragma unroll
    for (int i = 0; i < NCH / 4; i++) {
        int c = q * (NCH / 4) + i;
        float w = expf(cm[c] - M);
        ctx = fmaf(g_cacc[(b * NCH + c) * HID + h], w, ctx);
    }
    part[q][h] = ctx;
    __syncthreads();

    if (tid < 256) {
        float c4 = part[0][h] + part[1][h] + part[2][h] + part[3][h];
        float p = (c4 / D) * Wout[h];
#pragma unroll
        for (int off = 16; off; off >>= 1) p += __shfl_xor_sync(0xffffffffu, p, off);
        if ((tid & 31) == 0) wsum[tid >> 5] = p;
    }
    __syncthreads();
    if (tid == 0) {
        float v = 0.f;
#pragma unroll
        for (int w = 0; w < 8; w++) v += wsum[w];
        out[b] = v + bout[0];
    }
}

// ============================================================
extern "C" void kernel_launch(void* const* d_in, const int* in_sizes, int n_in,
                              void* d_out, int out_size) {
    const int*   X    = (const int*)d_in[0];
    const float* emb  = (const float*)d_in[1];
    const float* cw   = (const float*)d_in[2];
    const float* cb   = (const float*)d_in[3];
    const float* Mu   = (const float*)d_in[4];
    const float* Wout = (const float*)d_in[5];
    const float* bout = (const float*)d_in[6];
    float* out = (float*)d_out;

    k_gemm   <<<dim3(HID / 32, VOCAB / BM), 256>>>(emb, cw, cb);
    k_summary<<<dim3(NCH, BATCH), 256>>>(X);
    k_main   <<<dim3(NCH, BATCH), 256>>>(X, Mu);
    k_combine<<<BATCH, 1024>>>(Wout, bout, out);
}

// round 7
// speedup vs baseline: 2.8832x; 1.0607x over previous
#include <cuda_runtime.h>
#include <cuda_fp16.h>
#include <math.h>

#define VOCAB 32000
#define EMBED 256
#define HID   256
#define BATCH 32
#define SEQ   4096
#define NCH   64
#define CLEN  (SEQ / NCH)   // 64

// ---- scratch (device globals; no allocation allowed) ----
__device__ __half  g_embh[VOCAB * EMBED];    // fp16 embedding table
__device__ __half  g_cwh[512 * EMBED];       // fp16 conv weights
__device__ __half2 g_tab[VOCAB * HID];       // packed (f, g) per (vocab, channel)
__device__ float g_P[BATCH * NCH * HID];     // chunk decay product
__device__ float g_E[BATCH * NCH * HID];     // chunk local scan end (h0=0)
__device__ float g_cm[BATCH * NCH];          // chunk softmax max
__device__ float g_cd[BATCH * NCH];          // chunk softmax denom
__device__ float g_cacc[BATCH * NCH * HID];  // chunk weighted h accumulator

// ============================================================
// K-1: fp32 -> fp16 conversion prepass (emb then cw, 8 elems/thread)
// ============================================================
__global__ __launch_bounds__(256) void k_prep(const float* __restrict__ emb,
                                              const float* __restrict__ cw) {
    int base = (blockIdx.x * 256 + threadIdx.x) * 8;
    const float* src;
    __half* dst;
    if (base < VOCAB * EMBED) {
        src = emb + base;
        dst = g_embh + base;
    } else {
        int b2 = base - VOCAB * EMBED;
        src = cw + b2;
        dst = g_cwh + b2;
    }
    float4 a = *(const float4*)(src);
    float4 b = *(const float4*)(src + 4);
    __half2 h[4];
    h[0] = __floats2half2_rn(a.x, a.y);
    h[1] = __floats2half2_rn(a.z, a.w);
    h[2] = __floats2half2_rn(b.x, b.y);
    h[3] = __floats2half2_rn(b.z, b.w);
    *(uint4*)dst = *(uint4*)h;
}

// ============================================================
// K0: vocab table GEMM on tensor cores (fp16 in, fp32 acc)
//     C[v,n] = dot(emb[v,:], cw[map(n),:]) ; map pairs z/f cols.
//     BM=128, BN=64 (32 z + 32 f cols), BK=32, 8 warps,
//     cp.async double-buffered. Epilogue fuses act + half2 pack.
// ============================================================
#define BM 128
#define BN 64
#define BK 32
#define ASTR 40   // half elems per smem row (pad kills conflicts; 80B = 5*16B aligned)

struct GemmSmem {
    union {
        struct {
            __half Ah[2][BM * ASTR];
            __half Bh[2][BN * ASTR];
        } s;
        float Cs[BM * 66];
    } u;
};

#define MMA_F16(d, a, b) \
    asm volatile("mma.sync.aligned.m16n8k16.row.col.f32.f16.f16.f32 " \
                 "{%0,%1,%2,%3},{%4,%5,%6,%7},{%8,%9},{%0,%1,%2,%3};" \
                 : "+f"(d[0]), "+f"(d[1]), "+f"(d[2]), "+f"(d[3]) \
                 : "r"(a[0]), "r"(a[1]), "r"(a[2]), "r"(a[3]), "r"(b[0]), "r"(b[1]))

__device__ __forceinline__ void cp16(void* s, const void* g) {
    unsigned saddr = (unsigned)__cvta_generic_to_shared(s);
    asm volatile("cp.async.ca.shared.global [%0], [%1], 16;\n" :: "r"(saddr), "l"(g));
}

__global__ __launch_bounds__(256) void k_gemm(const float* __restrict__ cb) {
    __shared__ GemmSmem sm;
    const int t  = threadIdx.x;
    const int m0 = blockIdx.y * BM;
    const int h0 = blockIdx.x * 32;
    const int wid = t >> 5, lane = t & 31;
    const int wm = wid >> 1, wn = wid & 1;     // 4 x 2 warp grid
    const int lr = lane >> 2, lc = lane & 3;

    float acc[2][4][4];
#pragma unroll
    for (int i = 0; i < 2; i++)
#pragma unroll
        for (int j = 0; j < 4; j++)
#pragma unroll
            for (int r = 0; r < 4; r++) acc[i][j][r] = 0.f;

    // B row -> global row mapping (first 32 rows: z cols h0.., last 32: f cols 256+h0..)
    const int brow = t >> 2, bch = t & 3;
    const int bgr = (brow < 32) ? (h0 + brow) : (224 + h0 + brow);

    // stage issue: A 512 slots (2/thread), B 256 slots (1/thread); 16B each
#define ISSUE(kk, buf)                                                                  \
    {                                                                                   \
        _Pragma("unroll")                                                               \
        for (int i = 0; i < 2; i++) {                                                   \
            int slot = i * 256 + t;                                                     \
            int row = slot >> 2, ch = slot & 3;                                         \
            cp16(&sm.u.s.Ah[buf][row * ASTR + ch * 8],                                  \
                 g_embh + (size_t)(m0 + row) * EMBED + (kk) * BK + ch * 8);             \
        }                                                                               \
        cp16(&sm.u.s.Bh[buf][brow * ASTR + bch * 8],                                    \
             g_cwh + (size_t)bgr * EMBED + (kk) * BK + bch * 8);                        \
        asm volatile("cp.async.commit_group;\n" ::: "memory");                          \
    }

    ISSUE(0, 0)

    for (int kk = 0; kk < EMBED / BK; kk++) {
        const int buf = kk & 1;
        if (kk + 1 < EMBED / BK) {
            ISSUE(kk + 1, (kk + 1) & 1)
            asm volatile("cp.async.wait_group 1;\n" ::: "memory");
        } else {
            asm volatile("cp.async.wait_group 0;\n" ::: "memory");
        }
        __syncthreads();

#pragma unroll
        for (int kc = 0; kc < 2; kc++) {
            unsigned af[2][4];
#pragma unroll
            for (int mt = 0; mt < 2; mt++) {
                int r = wm * 32 + mt * 16 + lr;
                int base = r * ASTR + kc * 16 + 2 * lc;
                af[mt][0] = *(const unsigned*)&sm.u.s.Ah[buf][base];
                af[mt][1] = *(const unsigned*)&sm.u.s.Ah[buf][base + 8 * ASTR];
                af[mt][2] = *(const unsigned*)&sm.u.s.Ah[buf][base + 8];
                af[mt][3] = *(const unsigned*)&sm.u.s.Ah[buf][base + 8 * ASTR + 8];
            }
            unsigned bf[4][2];
#pragma unroll
            for (int nt = 0; nt < 4; nt++) {
                int n = wn * 32 + nt * 8 + lr;
                int base = n * ASTR + kc * 16 + 2 * lc;
                bf[nt][0] = *(const unsigned*)&sm.u.s.Bh[buf][base];
                bf[nt][1] = *(const unsigned*)&sm.u.s.Bh[buf][base + 8];
            }
#pragma unroll
            for (int mt = 0; mt < 2; mt++)
#pragma unroll
                for (int nt = 0; nt < 4; nt++)
                    MMA_F16(acc[mt][nt], af[mt], bf[nt]);
        }
        __syncthreads();
    }

    // epilogue: stash fp32 tiles, then activation + half2 pack
#pragma unroll
    for (int mt = 0; mt < 2; mt++)
#pragma unroll
        for (int nt = 0; nt < 4; nt++) {
            int r = wm * 32 + mt * 16 + lr;
            int col = wn * 32 + nt * 8 + 2 * lc;
            sm.u.Cs[r * 66 + col]           = acc[mt][nt][0];
            sm.u.Cs[r * 66 + col + 1]       = acc[mt][nt][1];
            sm.u.Cs[(r + 8) * 66 + col]     = acc[mt][nt][2];
            sm.u.Cs[(r + 8) * 66 + col + 1] = acc[mt][nt][3];
        }
    __syncthreads();

#pragma unroll
    for (int i = 0; i < 16; i++) {
        int o = i * 256 + t;
        int v = o >> 5, h = o & 31;
        float zp = sm.u.Cs[v * 66 + h]      + cb[h0 + h];
        float fp = sm.u.Cs[v * 66 + 32 + h] + cb[256 + h0 + h];
        float f  = 1.f / (1.f + expf(-fp));
        float g  = (1.f - f) * tanhf(zp);
        g_tab[(size_t)(m0 + v) * HID + h0 + h] = __floats2half2_rn(f, g);
    }
}

// ============================================================
// K2: per-chunk scan summaries  (P = prod f, E = local scan from 0)
// ============================================================
__global__ __launch_bounds__(256) void k_summary(const int* __restrict__ X) {
    const int b = blockIdx.y, c = blockIdx.x, h = threadIdx.x;
    __shared__ int xs[CLEN];
    if (h < CLEN) xs[h] = X[b * SEQ + c * CLEN + h];
    __syncthreads();
    float P = 1.f, E = 0.f;
#pragma unroll 8
    for (int t = 0; t < CLEN; t++) {
        float2 fg = __half22float2(g_tab[(size_t)xs[t] * HID + h]);
        E = fmaf(fg.x, E, fg.y);
        P *= fg.x;
    }
    int o = (b * NCH + c) * HID + h;
    g_P[o] = P;
    g_E[o] = E;
}

// ============================================================
// K3: replay each chunk with correct h_init; online softmax pooling
// ============================================================
__global__ __launch_bounds__(256) void k_main(const int* __restrict__ X,
                                              const float* __restrict__ Mu) {
    const int b = blockIdx.y, c = blockIdx.x;
    const int tid = threadIdx.x, h = threadIdx.x;
    __shared__ int   xs[CLEN];
    __shared__ float sred[8 * 257];
    __shared__ float lv[8];

    if (tid < CLEN) xs[tid] = X[b * SEQ + c * CLEN + tid];

    // reconstruct h at chunk start from summaries of chunks 0..c-1
    float hv = 0.f;
    for (int cc = 0; cc < c; cc++) {
        int o = (b * NCH + cc) * HID + h;
        hv = fmaf(g_P[o], hv, g_E[o]);
    }
    const float mu = Mu[h];
    __syncthreads();

    float m = -1e30f, d = 0.f, acc = 0.f;
    for (int t0 = 0; t0 < CLEN; t0 += 8) {
        float hb[8];
#pragma unroll
        for (int j = 0; j < 8; j++) {
            float2 fg = __half22float2(g_tab[(size_t)xs[t0 + j] * HID + h]);
            hv = fmaf(fg.x, hv, fg.y);
            hb[j] = hv;
            sred[j * 257 + tid] = hv * mu;
        }
        __syncthreads();
        {   // warp w reduces logit for timestep j=w
            int w = tid >> 5, lane = tid & 31;
            float s = 0.f;
#pragma unroll
            for (int k = 0; k < 8; k++) s += sred[w * 257 + lane + k * 32];
#pragma unroll
            for (int off = 16; off; off >>= 1) s += __shfl_xor_sync(0xffffffffu, s, off);
            if (lane == 0) lv[w] = s;
        }
        __syncthreads();
#pragma unroll
        for (int j = 0; j < 8; j++) {
            float l  = lv[j];
            float mn = fmaxf(m, l);
            float sc = expf(m - mn);
            float wg = expf(l - mn);
            d   = d   * sc + wg;
            acc = acc * sc + hb[j] * wg;
            m = mn;
        }
    }
    if (tid == 0) { g_cm[b * NCH + c] = m; g_cd[b * NCH + c] = d; }
    g_cacc[(b * NCH + c) * HID + h] = acc;
}

// ============================================================
// K4a: init output with bias
// ============================================================
__global__ void k_init(const float* __restrict__ bout, float* __restrict__ out) {
    if (threadIdx.x < BATCH) out[threadIdx.x] = bout[0];
}

// ============================================================
// K4b: combine chunks: grid (8 chunk-groups, 32 batches), atomic partials
// ============================================================
#define CGRP 8
__global__ __launch_bounds__(256) void k_combine(const float* __restrict__ Wout,
                                                 float* __restrict__ out) {
    const int b = blockIdx.y, cg = blockIdx.x;
    const int tid = threadIdx.x, h = threadIdx.x;
    __shared__ float cm[NCH], cd[NCH], wsum[8];
    if (tid < NCH) {
        cm[tid] = g_cm[b * NCH + tid];
        cd[tid] = g_cd[b * NCH + tid];
    }
    __syncthreads();
    float M = -1e30f;
#pragma unroll
    for (int c = 0; c < NCH; c++) M = fmaxf(M, cm[c]);
    float D = 0.f;
#pragma unroll
    for (int c = 0; c < NCH; c++) D += cd[c] * expf(cm[c] - M);

    float ctx = 0.f;
#pragma unroll
    for (int i = 0; i < CGRP; i++) {
        int c = cg * CGRP + i;
        ctx = fmaf(g_cacc[(b * NCH + c) * HID + h], expf(cm[c] - M), ctx);
    }
    float p = (ctx / D) * Wout[h];
#pragma unroll
    for (int off = 16; off; off >>= 1) p += __shfl_xor_sync(0xffffffffu, p, off);
    if ((tid & 31) == 0) wsum[tid >> 5] = p;
    __syncthreads();
    if (tid == 0) {
        float v = 0.f;
#pragma unroll
        for (int w = 0; w < 8; w++) v += wsum[w];
        atomicAdd(out + b, v);
    }
}

// ============================================================
extern "C" void kernel_launch(void* const* d_in, const int* in_sizes, int n_in,
                              void* d_out, int out_size) {
    const int*   X    = (const int*)d_in[0];
    const float* emb  = (const float*)d_in[1];
    const float* cw   = (const float*)d_in[2];
    const float* cb   = (const float*)d_in[3];
    const float* Mu   = (const float*)d_in[4];
    const float* Wout = (const float*)d_in[5];
    const float* bout = (const float*)d_in[6];
    float* out = (float*)d_out;

    k_prep   <<<(VOCAB * EMBED + 512 * EMBED) / (256 * 8), 256>>>(emb, cw);
    k_gemm   <<<dim3(HID / 32, VOCAB / BM), 256>>>(cb);
    k_init   <<<1, 32>>>(bout, out);
    k_summary<<<dim3(NCH, BATCH), 256>>>(X);
    k_main   <<<dim3(NCH, BATCH), 256>>>(X, Mu);
    k_combine<<<dim3(NCH / CGRP, BATCH), 256>>>(Wout, out);
}